// round 6
// baseline (speedup 1.0000x reference)
#include <cuda_runtime.h>
#include <cstdint>

#define BATCH 8
#define LSEQ  2048
#define DCH   256
#define NST   64

// ---- device scratch (static: no dynamic allocation allowed) ----
__device__ float gA[NST * NST];
__device__ float gAinv[NST * NST];
__device__ float gdt[DCH];
__device__ float gDA[DCH * NST * NST];
__device__ float gWT[DCH * DCH];                 // W_out transposed [din][dout]
__device__ float gKpad[(LSEQ + 32) * DCH];       // 32 zero rows then k[l][d]
__device__ float gY[BATCH * LSEQ * DCH];

typedef unsigned long long u64t;

__device__ __forceinline__ float softplusf(float x) {
    return (x > 20.0f) ? x : log1pf(expf(x));
}

__device__ __forceinline__ float red4(float v) {
    v += __shfl_down_sync(0xffffffffu, v, 2);
    v += __shfl_down_sync(0xffffffffu, v, 1);
    return v;
}

__device__ __forceinline__ u64t pk2(float lo, float hi) {
    u64t r;
    asm("mov.b64 %0, {%1, %2};" : "=l"(r)
        : "r"(__float_as_uint(lo)), "r"(__float_as_uint(hi)));
    return r;
}
__device__ __forceinline__ u64t ffma2(u64t a, u64t b, u64t c) {
    u64t d;
    asm("fma.rn.f32x2 %0, %1, %2, %3;" : "=l"(d) : "l"(a), "l"(b), "l"(c));
    return d;
}
__device__ __forceinline__ void upk2(u64t v, float& lo, float& hi) {
    unsigned a, b;
    asm("mov.b64 {%0, %1}, %2;" : "=r"(a), "=r"(b) : "l"(v));
    lo = __uint_as_float(a);
    hi = __uint_as_float(b);
}

// C = A @ B for 64x64 tiles in shared, row stride 65. 256 threads.
// Leading+trailing barriers so call sites stay simple.
__device__ void mm64(const float* __restrict__ A, const float* __restrict__ B,
                     float* __restrict__ C) {
    __syncthreads();
    int n = threadIdx.x & 63;
    int g = threadIdx.x >> 6;
    float acc[16];
#pragma unroll
    for (int q = 0; q < 16; ++q) acc[q] = 0.0f;
    for (int j = 0; j < 64; ++j) {
        float a = A[n * 65 + j];
#pragma unroll
        for (int q = 0; q < 16; ++q)
            acc[q] = fmaf(a, B[j * 65 + g * 16 + q], acc[q]);
    }
#pragma unroll
    for (int q = 0; q < 16; ++q) C[n * 65 + g * 16 + q] = acc[q];
    __syncthreads();
}

// ---- K0: A=softplus(log_A); dt; Ainv=(A+1e-6 I)^-1 (Gauss-Jordan, pivoted) ----
__global__ void k0_prep(const float* __restrict__ log_A,
                        const float* __restrict__ log_delta) {
    __shared__ float Ms[64][130];
    __shared__ float fs[64];
    __shared__ int piv_s;
    int tid = threadIdx.x;

    for (int idx = tid; idx < 64 * 64; idx += 256) {
        int n = idx >> 6, m = idx & 63;
        float a = softplusf(log_A[idx]);
        gA[idx] = a;
        Ms[n][m] = a + ((n == m) ? 1e-6f : 0.0f);
        Ms[n][64 + m] = (n == m) ? 1.0f : 0.0f;
    }
    gdt[tid] = softplusf(log_delta[tid]) + 1e-6f;
    __syncthreads();

    for (int p = 0; p < 64; ++p) {
        if (tid == 0) {
            int best = p; float bv = fabsf(Ms[p][p]);
            for (int r = p + 1; r < 64; ++r) {
                float v = fabsf(Ms[r][p]);
                if (v > bv) { bv = v; best = r; }
            }
            piv_s = best;
        }
        __syncthreads();
        int pr = piv_s;
        if (pr != p) {
            for (int c = tid; c < 128; c += 256) {
                float t = Ms[p][c]; Ms[p][c] = Ms[pr][c]; Ms[pr][c] = t;
            }
        }
        __syncthreads();
        float inv = 1.0f / Ms[p][p];
        __syncthreads();
        for (int c = tid; c < 128; c += 256) Ms[p][c] *= inv;
        __syncthreads();
        if (tid < 64) fs[tid] = Ms[tid][p];
        __syncthreads();
        for (int idx = tid; idx < 64 * 128; idx += 256) {
            int i = idx >> 7, c = idx & 127;
            if (i != p) Ms[i][c] -= fs[i] * Ms[p][c];
        }
        __syncthreads();
    }
    for (int idx = tid; idx < 64 * 64; idx += 256) {
        int n = idx >> 6, m = idx & 63;
        gAinv[idx] = Ms[n][64 + m];
    }
}

// ---- K0b: transpose W_out ----
__global__ void k0b_wt(const float* __restrict__ W) {
    int r = blockIdx.x, c = threadIdx.x;
    gWT[c * 256 + r] = W[r * 256 + c];
}

// ---- K1: dA_d = expm(dt_d * A). One block per d. ----
__global__ void k1_expm() {
    extern __shared__ float sm[];
    float* Ts = sm;
    float* Ps = sm + 64 * 65;
    float* Qs = sm + 2 * 64 * 65;
    __shared__ float colsum[64];
    __shared__ int s_scal, s_K;
    int tid = threadIdx.x;
    int d = blockIdx.x;
    float dt = gdt[d];

    for (int idx = tid; idx < 64 * 64; idx += 256) {
        int n = idx >> 6, m = idx & 63;
        Ts[n * 65 + m] = gA[idx] * dt;
    }
    __syncthreads();
    if (tid < 64) {
        float s = 0.0f;
        for (int n = 0; n < 64; ++n) s += fabsf(Ts[n * 65 + tid]);
        colsum[tid] = s;
    }
    __syncthreads();
    if (tid == 0) {
        float mx = 0.0f;
        for (int m = 0; m < 64; ++m) mx = fmaxf(mx, colsum[m]);
        int sc = 0; float nn = mx;
        while (nn > 0.5f) { nn *= 0.5f; sc++; }
        int K;
        if      (nn < 7e-3f)  K = 3;
        else if (nn < 0.026f) K = 4;
        else if (nn < 0.065f) K = 5;
        else if (nn < 0.126f) K = 6;
        else if (nn < 0.212f) K = 7;
        else if (nn < 0.32f)  K = 8;
        else if (nn < 0.45f)  K = 9;
        else                  K = 10;
        s_scal = sc; s_K = K;
    }
    __syncthreads();
    int sc = s_scal, K = s_K;
    if (sc > 0) {
        float f = ldexpf(1.0f, -sc);
        for (int idx = tid; idx < 64 * 64; idx += 256) {
            int n = idx >> 6, m = idx & 63;
            Ts[n * 65 + m] *= f;
        }
        __syncthreads();
    }
    {   // P = I + T/K
        float invK = 1.0f / (float)K;
        for (int idx = tid; idx < 64 * 64; idx += 256) {
            int n = idx >> 6, m = idx & 63;
            Ps[n * 65 + m] = ((n == m) ? 1.0f : 0.0f) + Ts[n * 65 + m] * invK;
        }
    }
    for (int kk = K - 1; kk >= 1; --kk) {  // P = I + T*P/kk
        mm64(Ts, Ps, Qs);
        float invk = 1.0f / (float)kk;
        for (int idx = tid; idx < 64 * 64; idx += 256) {
            int n = idx >> 6, m = idx & 63;
            Ps[n * 65 + m] = ((n == m) ? 1.0f : 0.0f) + Qs[n * 65 + m] * invk;
        }
    }
    for (int q = 0; q < sc; ++q) {
        mm64(Ps, Ps, Qs);
        for (int idx = tid; idx < 64 * 64; idx += 256) {
            int n = idx >> 6, m = idx & 63;
            Ps[n * 65 + m] = Qs[n * 65 + m];
        }
    }
    __syncthreads();
    for (int idx = tid; idx < 64 * 64; idx += 256) {
        int n = idx >> 6, m = idx & 63;
        gDA[(size_t)d * 4096 + idx] = Ps[n * 65 + m];
    }
}

// ---- K2: build kpad. k[64j+i] = u_i . v_j ; u_i=(dA^T)^i C ; v_{j+1}=dA^64 v_j ----
__global__ void k2_kernelgen(const float* __restrict__ Bp,
                             const float* __restrict__ Cp) {
    extern __shared__ float sm[];
    float* dAs = sm;
    float* Us  = sm + 64 * 65;
    float* Ps  = sm + 2 * 64 * 65;
    float* Qs  = sm + 3 * 64 * 65;
    __shared__ float bvec[64], xs[64], dBv[64], va[64], vb[64];
    int tid = threadIdx.x;
    int d = blockIdx.x;
    int n4 = tid >> 2, p4 = tid & 3;

    for (int idx = tid; idx < 64 * 64; idx += 256) {
        int n = idx >> 6, m = idx & 63;
        dAs[n * 65 + m] = gDA[(size_t)d * 4096 + idx];
        Ps[n * 65 + m]  = gAinv[idx];
    }
    if (tid < 64) bvec[tid] = Bp[d * 64 + tid];
    if (tid < 32) gKpad[tid * 256 + d] = 0.0f;
    __syncthreads();

    { // xs = Ainv * Bp[d]
        float s = 0.0f;
#pragma unroll
        for (int q = 0; q < 16; ++q)
            s = fmaf(Ps[n4 * 65 + p4 * 16 + q], bvec[p4 * 16 + q], s);
        s = red4(s);
        if (p4 == 0) xs[n4] = s;
    }
    __syncthreads();
    { // dBv = (dA - I) xs
        float s = 0.0f;
#pragma unroll
        for (int q = 0; q < 16; ++q)
            s = fmaf(dAs[n4 * 65 + p4 * 16 + q], xs[p4 * 16 + q], s);
        s = red4(s);
        if (p4 == 0) dBv[n4] = s - xs[n4];
    }
    if (tid < 64) Us[tid] = Cp[d * 64 + tid];  // u_0
    __syncthreads();
    for (int i = 1; i < 64; ++i) {             // u_i = dA^T u_{i-1}
        float s = 0.0f;
#pragma unroll
        for (int q = 0; q < 16; ++q)
            s = fmaf(dAs[(p4 * 16 + q) * 65 + n4], Us[(i - 1) * 65 + p4 * 16 + q], s);
        s = red4(s);
        if (p4 == 0) Us[i * 65 + n4] = s;
        __syncthreads();
    }
    // P = dA^64 (6 squarings), result in Ps
    mm64(dAs, dAs, Qs);
    mm64(Qs, Qs, Ps);
    mm64(Ps, Ps, Qs);
    mm64(Qs, Qs, Ps);
    mm64(Ps, Ps, Qs);
    mm64(Qs, Qs, Ps);

    if (tid < 64) va[tid] = dBv[tid];
    __syncthreads();
    for (int j = 0; j < 32; ++j) {
        float* cur = (j & 1) ? vb : va;
        float* nxt = (j & 1) ? va : vb;
        {   // k[64j + n4] = u_{n4} . v_j
            float s = 0.0f;
#pragma unroll
            for (int q = 0; q < 16; ++q)
                s = fmaf(Us[n4 * 65 + p4 * 16 + q], cur[p4 * 16 + q], s);
            s = red4(s);
            if (p4 == 0)
                gKpad[(size_t)(32 + j * 64 + n4) * 256 + d] = s;
        }
        {   // v_{j+1} = P v_j
            float s = 0.0f;
#pragma unroll
            for (int q = 0; q < 16; ++q)
                s = fmaf(Ps[n4 * 65 + p4 * 16 + q], cur[p4 * 16 + q], s);
            s = red4(s);
            if (p4 == 0) nxt[n4] = s;
        }
        __syncthreads();
    }
}

// ---- K3: causal conv, f32x2 packed FMA. thread = channel d, 32 outputs. ----
// Output pair (2i,2i+1) needs adjacent weights kw[32+2i-u], kw[33+2i-u]:
// pre-pack the 64-wide k window into even-start (pe) and odd-start (po) pairs,
// select by parity of u (compile-time: u-loop fully unrolled).
__global__ void __launch_bounds__(256, 1) k3_conv(const float* __restrict__ x) {
    int bx = blockIdx.x;
    int tile = 63 - (bx >> 3);   // heavy (triangular) tiles launch first
    int b = bx & 7;
    int d = threadIdx.x;
    int t0 = tile * 32;
    const float* xb = x + (size_t)b * LSEQ * DCH + d;
    u64t acc2[16];
#pragma unroll
    for (int i = 0; i < 16; ++i) acc2[i] = 0ull;

    for (int c = 0; c <= tile; ++c) {
        int base = t0 - c * 32;
        const float* kp = gKpad + (size_t)base * DCH + d;
        float kw[64];
#pragma unroll
        for (int w = 0; w < 64; ++w) kw[w] = kp[(size_t)w * DCH];
        u64t pe[32], po[31];
#pragma unroll
        for (int j = 1; j < 32; ++j) pe[j] = pk2(kw[2 * j], kw[2 * j + 1]);
#pragma unroll
        for (int j = 0; j < 31; ++j) po[j] = pk2(kw[2 * j + 1], kw[2 * j + 2]);
        const float* xp = xb + (size_t)c * 32 * DCH;
#pragma unroll
        for (int u = 0; u < 32; ++u) {
            float xv = xp[(size_t)u * DCH];
            u64t xv2 = pk2(xv, xv);
            if ((u & 1) == 0) {
                const int j0 = 16 - u / 2;          // pe[j0+i] = (kw[32+2i-u], kw[33+2i-u])
#pragma unroll
                for (int i = 0; i < 16; ++i)
                    acc2[i] = ffma2(pe[j0 + i], xv2, acc2[i]);
            } else {
                const int j0 = 15 - (u - 1) / 2;    // po[j0+i] = (kw[32+2i-u], kw[33+2i-u])
#pragma unroll
                for (int i = 0; i < 16; ++i)
                    acc2[i] = ffma2(po[j0 + i], xv2, acc2[i]);
            }
        }
    }
    float* yo = gY + ((size_t)b * LSEQ + t0) * DCH + d;
#pragma unroll
    for (int i = 0; i < 16; ++i) {
        float lo, hi;
        upk2(acc2[i], lo, hi);
        yo[(size_t)(2 * i) * DCH]     = lo;
        yo[(size_t)(2 * i + 1) * DCH] = hi;
    }
}

// ---- K4: out = (y + x*skip) @ W^T + b, f32x2 along the reduction dim. ----
// acc2[r] accumulates (partial_even, partial_odd); final = lo + hi.
__global__ void __launch_bounds__(256) k4_out(const float* __restrict__ x,
        const float* __restrict__ skip_D, const float* __restrict__ b_out,
        float* __restrict__ out) {
    __shared__ float zs[32][256];
    int row0 = blockIdx.x * 32;
    int tid = threadIdx.x;
    for (int idx = tid; idx < 32 * 256; idx += 256) {
        int r = idx >> 8, dd = idx & 255;
        size_t g = (size_t)(row0 + r) * 256 + dd;
        zs[r][dd] = gY[g] + x[g] * skip_D[dd];
    }
    __syncthreads();
    u64t acc2[32];
#pragma unroll
    for (int r = 0; r < 32; ++r) acc2[r] = 0ull;
    for (int kk = 0; kk < 256; kk += 4) {
        float wa = gWT[(kk + 0) * 256 + tid];
        float wb = gWT[(kk + 1) * 256 + tid];
        float wc = gWT[(kk + 2) * 256 + tid];
        float wd = gWT[(kk + 3) * 256 + tid];
        u64t w01 = pk2(wa, wb);
        u64t w23 = pk2(wc, wd);
#pragma unroll
        for (int r = 0; r < 32; ++r) {
            u64t z01 = *(const u64t*)&zs[r][kk];      // (z[kk], z[kk+1])
            u64t z23 = *(const u64t*)&zs[r][kk + 2];  // (z[kk+2], z[kk+3])
            acc2[r] = ffma2(z01, w01, acc2[r]);
            acc2[r] = ffma2(z23, w23, acc2[r]);
        }
    }
    float bo = b_out[tid];
#pragma unroll
    for (int r = 0; r < 32; ++r) {
        float lo, hi;
        upk2(acc2[r], lo, hi);
        out[(size_t)(row0 + r) * 256 + tid] = lo + hi + bo;
    }
}

extern "C" void kernel_launch(void* const* d_in, const int* in_sizes, int n_in,
                              void* d_out, int out_size) {
    const float* x         = (const float*)d_in[0];
    const float* log_A     = (const float*)d_in[1];
    const float* Bp        = (const float*)d_in[2];
    const float* Cp        = (const float*)d_in[3];
    const float* log_delta = (const float*)d_in[4];
    const float* skip_D    = (const float*)d_in[5];
    const float* W_out     = (const float*)d_in[6];
    const float* b_out     = (const float*)d_in[7];
    float* out = (float*)d_out;

    const int shm1 = 3 * 64 * 65 * (int)sizeof(float);   // 49920 B
    const int shm2 = 4 * 64 * 65 * (int)sizeof(float);   // 66560 B
    cudaFuncSetAttribute(k1_expm, cudaFuncAttributeMaxDynamicSharedMemorySize, shm1);
    cudaFuncSetAttribute(k2_kernelgen, cudaFuncAttributeMaxDynamicSharedMemorySize, shm2);

    k0_prep<<<1, 256>>>(log_A, log_delta);
    k0b_wt<<<256, 256>>>(W_out);
    k1_expm<<<256, 256, shm1>>>();
    k2_kernelgen<<<256, 256, shm2>>>(Bp, Cp);
    k3_conv<<<512, 256>>>(x);
    k4_out<<<512, 256>>>(x, skip_D, b_out, out);
}

// round 8
// speedup vs baseline: 1.0693x; 1.0693x over previous
#include <cuda_runtime.h>
#include <cstdint>

#define BATCH 8
#define LSEQ  2048
#define DCH   256
#define NST   64

// ---- device scratch (static: no dynamic allocation allowed) ----
__device__ float gA[NST * NST];
__device__ float gAinv[NST * NST];
__device__ float gdt[DCH];
__device__ float gDA[DCH * NST * NST];
__device__ float gWT[DCH * DCH];                 // W_out transposed [din][dout]
__device__ float gKpad[(LSEQ + 32) * DCH];       // 32 zero rows then k[l][d]
__device__ float gY[BATCH * LSEQ * DCH];

typedef unsigned long long u64t;

__device__ __forceinline__ float softplusf(float x) {
    return (x > 20.0f) ? x : log1pf(expf(x));
}

__device__ __forceinline__ float red8(float v) {
    v += __shfl_down_sync(0xffffffffu, v, 4);
    v += __shfl_down_sync(0xffffffffu, v, 2);
    v += __shfl_down_sync(0xffffffffu, v, 1);
    return v;
}

__device__ __forceinline__ u64t pk2(float lo, float hi) {
    u64t r;
    asm("mov.b64 %0, {%1, %2};" : "=l"(r)
        : "r"(__float_as_uint(lo)), "r"(__float_as_uint(hi)));
    return r;
}
__device__ __forceinline__ u64t ffma2(u64t a, u64t b, u64t c) {
    u64t d;
    asm("fma.rn.f32x2 %0, %1, %2, %3;" : "=l"(d) : "l"(a), "l"(b), "l"(c));
    return d;
}
__device__ __forceinline__ void upk2(u64t v, float& lo, float& hi) {
    unsigned a, b;
    asm("mov.b64 {%0, %1}, %2;" : "=r"(a), "=r"(b) : "l"(v));
    lo = __uint_as_float(a);
    hi = __uint_as_float(b);
}

// C = A @ B for 64x64 tiles in shared, row stride 65. 512 threads.
// Leading+trailing barriers so call sites stay simple.
__device__ void mm64(const float* __restrict__ A, const float* __restrict__ B,
                     float* __restrict__ C) {
    __syncthreads();
    int n = threadIdx.x & 63;
    int g = threadIdx.x >> 6;   // 0..7
    float acc[8];
#pragma unroll
    for (int q = 0; q < 8; ++q) acc[q] = 0.0f;
    for (int j = 0; j < 64; ++j) {
        float a = A[n * 65 + j];
#pragma unroll
        for (int q = 0; q < 8; ++q)
            acc[q] = fmaf(a, B[j * 65 + g * 8 + q], acc[q]);
    }
#pragma unroll
    for (int q = 0; q < 8; ++q) C[n * 65 + g * 8 + q] = acc[q];
    __syncthreads();
}

// ---- K0: A=softplus(log_A); dt; Ainv=(A+1e-6 I)^-1 (Gauss-Jordan, pivoted) ----
__global__ void k0_prep(const float* __restrict__ log_A,
                        const float* __restrict__ log_delta) {
    __shared__ float Ms[64][130];
    __shared__ float fs[64];
    __shared__ int piv_s;
    int tid = threadIdx.x;

    for (int idx = tid; idx < 64 * 64; idx += 256) {
        int n = idx >> 6, m = idx & 63;
        float a = softplusf(log_A[idx]);
        gA[idx] = a;
        Ms[n][m] = a + ((n == m) ? 1e-6f : 0.0f);
        Ms[n][64 + m] = (n == m) ? 1.0f : 0.0f;
    }
    gdt[tid] = softplusf(log_delta[tid]) + 1e-6f;
    __syncthreads();

    for (int p = 0; p < 64; ++p) {
        if (tid == 0) {
            int best = p; float bv = fabsf(Ms[p][p]);
            for (int r = p + 1; r < 64; ++r) {
                float v = fabsf(Ms[r][p]);
                if (v > bv) { bv = v; best = r; }
            }
            piv_s = best;
        }
        __syncthreads();
        int pr = piv_s;
        if (pr != p) {
            for (int c = tid; c < 128; c += 256) {
                float t = Ms[p][c]; Ms[p][c] = Ms[pr][c]; Ms[pr][c] = t;
            }
        }
        __syncthreads();
        float inv = 1.0f / Ms[p][p];
        __syncthreads();
        for (int c = tid; c < 128; c += 256) Ms[p][c] *= inv;
        __syncthreads();
        if (tid < 64) fs[tid] = Ms[tid][p];
        __syncthreads();
        for (int idx = tid; idx < 64 * 128; idx += 256) {
            int i = idx >> 7, c = idx & 127;
            if (i != p) Ms[i][c] -= fs[i] * Ms[p][c];
        }
        __syncthreads();
    }
    for (int idx = tid; idx < 64 * 64; idx += 256) {
        int n = idx >> 6, m = idx & 63;
        gAinv[idx] = Ms[n][64 + m];
    }
}

// ---- K0b: transpose W_out ----
__global__ void k0b_wt(const float* __restrict__ W) {
    int r = blockIdx.x, c = threadIdx.x;
    gWT[c * 256 + r] = W[r * 256 + c];
}

// ---- K1: dA_d = expm(dt_d * A). One block (512 thr) per d. ----
__global__ void k1_expm() {
    extern __shared__ float sm[];
    float* Ts = sm;
    float* Ps = sm + 64 * 65;
    float* Qs = sm + 2 * 64 * 65;
    __shared__ float colsum[64];
    __shared__ int s_scal, s_K;
    int tid = threadIdx.x;
    int d = blockIdx.x;
    float dt = gdt[d];

    for (int idx = tid; idx < 64 * 64; idx += 512) {
        int n = idx >> 6, m = idx & 63;
        Ts[n * 65 + m] = gA[idx] * dt;
    }
    __syncthreads();
    if (tid < 64) {
        float s = 0.0f;
        for (int n = 0; n < 64; ++n) s += fabsf(Ts[n * 65 + tid]);
        colsum[tid] = s;
    }
    __syncthreads();
    if (tid == 0) {
        float mx = 0.0f;
        for (int m = 0; m < 64; ++m) mx = fmaxf(mx, colsum[m]);
        int sc = 0; float nn = mx;
        while (nn > 0.5f) { nn *= 0.5f; sc++; }
        int K;
        if      (nn < 7e-3f)  K = 3;
        else if (nn < 0.026f) K = 4;
        else if (nn < 0.065f) K = 5;
        else if (nn < 0.126f) K = 6;
        else if (nn < 0.212f) K = 7;
        else if (nn < 0.32f)  K = 8;
        else if (nn < 0.45f)  K = 9;
        else                  K = 10;
        s_scal = sc; s_K = K;
    }
    __syncthreads();
    int sc = s_scal, K = s_K;
    if (sc > 0) {
        float f = ldexpf(1.0f, -sc);
        for (int idx = tid; idx < 64 * 64; idx += 512) {
            int n = idx >> 6, m = idx & 63;
            Ts[n * 65 + m] *= f;
        }
        __syncthreads();
    }
    {   // P = I + T/K
        float invK = 1.0f / (float)K;
        for (int idx = tid; idx < 64 * 64; idx += 512) {
            int n = idx >> 6, m = idx & 63;
            Ps[n * 65 + m] = ((n == m) ? 1.0f : 0.0f) + Ts[n * 65 + m] * invK;
        }
    }
    for (int kk = K - 1; kk >= 1; --kk) {  // P = I + T*P/kk
        mm64(Ts, Ps, Qs);
        float invk = 1.0f / (float)kk;
        for (int idx = tid; idx < 64 * 64; idx += 512) {
            int n = idx >> 6, m = idx & 63;
            Ps[n * 65 + m] = ((n == m) ? 1.0f : 0.0f) + Qs[n * 65 + m] * invk;
        }
    }
    for (int q = 0; q < sc; ++q) {
        mm64(Ps, Ps, Qs);
        for (int idx = tid; idx < 64 * 64; idx += 512) {
            int n = idx >> 6, m = idx & 63;
            Ps[n * 65 + m] = Qs[n * 65 + m];
        }
    }
    __syncthreads();
    for (int idx = tid; idx < 64 * 64; idx += 512) {
        int n = idx >> 6, m = idx & 63;
        gDA[(size_t)d * 4096 + idx] = Ps[n * 65 + m];
    }
}

// ---- K2: build kpad. k[64j+i] = u_i . v_j ; u_i=(dA^T)^i C ; v_{j+1}=dA^64 v_j ----
// 512 threads. V staged in shared; final k-tile = one parallel 64x32 matmul.
__global__ void k2_kernelgen(const float* __restrict__ Bp,
                             const float* __restrict__ Cp) {
    extern __shared__ float sm[];
    float* dAs = sm;                  // 64x65
    float* Ps  = sm + 64 * 65;        // Ainv, then squaring ping-pong -> dA^64
    float* Qs  = sm + 2 * 64 * 65;
    float* Us  = sm + 3 * 64 * 65;    // Us[i*65+n] : u_i
    float* Vs  = sm + 4 * 64 * 65;    // Vs[n*33+j] : v_j
    __shared__ float bvec[64], xs[64], dBv[64];
    int tid = threadIdx.x;
    int d = blockIdx.x;
    int n8 = tid >> 3, p8 = tid & 7;

    for (int idx = tid; idx < 64 * 64; idx += 512) {
        int n = idx >> 6, m = idx & 63;
        dAs[n * 65 + m] = gDA[(size_t)d * 4096 + idx];
        Ps[n * 65 + m]  = gAinv[idx];
    }
    if (tid < 64) bvec[tid] = Bp[d * 64 + tid];
    if (tid < 32) gKpad[tid * 256 + d] = 0.0f;
    __syncthreads();

    { // xs = Ainv * Bp[d]
        float s = 0.0f;
#pragma unroll
        for (int q = 0; q < 8; ++q)
            s = fmaf(Ps[n8 * 65 + p8 * 8 + q], bvec[p8 * 8 + q], s);
        s = red8(s);
        if (p8 == 0) xs[n8] = s;
    }
    __syncthreads();
    { // dBv = (dA - I) xs
        float s = 0.0f;
#pragma unroll
        for (int q = 0; q < 8; ++q)
            s = fmaf(dAs[n8 * 65 + p8 * 8 + q], xs[p8 * 8 + q], s);
        s = red8(s);
        if (p8 == 0) dBv[n8] = s - xs[n8];
    }
    if (tid < 64) Us[tid] = Cp[d * 64 + tid];  // u_0
    __syncthreads();
    for (int i = 1; i < 64; ++i) {             // u_i = dA^T u_{i-1}
        float s = 0.0f;
#pragma unroll
        for (int q = 0; q < 8; ++q)
            s = fmaf(dAs[(p8 * 8 + q) * 65 + n8], Us[(i - 1) * 65 + p8 * 8 + q], s);
        s = red8(s);
        if (p8 == 0) Us[i * 65 + n8] = s;
        __syncthreads();
    }
    // P = dA^64 (6 squarings), result in Ps
    mm64(dAs, dAs, Qs);
    mm64(Qs, Qs, Ps);
    mm64(Ps, Ps, Qs);
    mm64(Qs, Qs, Ps);
    mm64(Ps, Ps, Qs);
    mm64(Qs, Qs, Ps);

    if (tid < 64) Vs[tid * 33 + 0] = dBv[tid];
    __syncthreads();
    for (int j = 1; j < 32; ++j) {             // v_j = P v_{j-1}
        float s = 0.0f;
#pragma unroll
        for (int q = 0; q < 8; ++q)
            s = fmaf(Ps[n8 * 65 + p8 * 8 + q], Vs[(p8 * 8 + q) * 33 + (j - 1)], s);
        s = red8(s);
        if (p8 == 0) Vs[n8 * 33 + j] = s;
        __syncthreads();
    }
    // k tile: k[64j+i] = sum_n Us[i][n] Vs[n][j]; 2048 outputs, 4/thread
    {
        int i  = tid >> 3;
        int j0 = (tid & 7) * 4;
        float s0 = 0.0f, s1 = 0.0f, s2 = 0.0f, s3 = 0.0f;
        for (int n = 0; n < 64; ++n) {
            float uv = Us[i * 65 + n];
            s0 = fmaf(uv, Vs[n * 33 + j0 + 0], s0);
            s1 = fmaf(uv, Vs[n * 33 + j0 + 1], s1);
            s2 = fmaf(uv, Vs[n * 33 + j0 + 2], s2);
            s3 = fmaf(uv, Vs[n * 33 + j0 + 3], s3);
        }
        gKpad[(size_t)(32 + (j0 + 0) * 64 + i) * 256 + d] = s0;
        gKpad[(size_t)(32 + (j0 + 1) * 64 + i) * 256 + d] = s1;
        gKpad[(size_t)(32 + (j0 + 2) * 64 + i) * 256 + d] = s2;
        gKpad[(size_t)(32 + (j0 + 3) * 64 + i) * 256 + d] = s3;
    }
}

// ---- K3: causal conv, f32x2 packed FMA. thread = channel d. ----
// acc2[i] holds output pair (t0+i, t0+i+16); weight pair pq[w]=(k[w],k[w+16]),
// so every u uses pq[32+i-u] (w in [1,47]) — no parity split, no kw array.
__global__ void __launch_bounds__(256, 1) k3_conv(const float* __restrict__ x) {
    int bx = blockIdx.x;
    int tile = 63 - (bx >> 3);   // heavy (triangular) tiles launch first
    int b = bx & 7;
    int d = threadIdx.x;
    int t0 = tile * 32;
    const float* xb = x + (size_t)b * LSEQ * DCH + d;
    u64t acc2[16];
#pragma unroll
    for (int i = 0; i < 16; ++i) acc2[i] = 0ull;

    for (int c = 0; c <= tile; ++c) {
        int base = t0 - c * 32;
        const float* kp = gKpad + (size_t)base * DCH + d;
        u64t pq[48];
#pragma unroll
        for (int w = 1; w < 48; ++w)
            pq[w] = pk2(kp[(size_t)w * DCH], kp[(size_t)(w + 16) * DCH]);
        const float* xp = xb + (size_t)c * 32 * DCH;
#pragma unroll
        for (int u = 0; u < 32; ++u) {
            float xv = xp[(size_t)u * DCH];
            u64t xv2 = pk2(xv, xv);
#pragma unroll
            for (int i = 0; i < 16; ++i)
                acc2[i] = ffma2(pq[32 + i - u], xv2, acc2[i]);
        }
    }
    float* yo = gY + ((size_t)b * LSEQ + t0) * DCH + d;
#pragma unroll
    for (int i = 0; i < 16; ++i) {
        float lo, hi;
        upk2(acc2[i], lo, hi);
        yo[(size_t)i * DCH]        = lo;
        yo[(size_t)(i + 16) * DCH] = hi;
    }
}

// ---- K4: out = (y + x*skip) @ W^T + b, f32x2 along the reduction dim. ----
__global__ void __launch_bounds__(256) k4_out(const float* __restrict__ x,
        const float* __restrict__ skip_D, const float* __restrict__ b_out,
        float* __restrict__ out) {
    __shared__ float zs[32][256];
    int row0 = blockIdx.x * 32;
    int tid = threadIdx.x;
    for (int idx = tid; idx < 32 * 256; idx += 256) {
        int r = idx >> 8, dd = idx & 255;
        size_t g = (size_t)(row0 + r) * 256 + dd;
        zs[r][dd] = gY[g] + x[g] * skip_D[dd];
    }
    __syncthreads();
    u64t acc2[32];
#pragma unroll
    for (int r = 0; r < 32; ++r) acc2[r] = 0ull;
    for (int kk = 0; kk < 256; kk += 4) {
        float wa = gWT[(kk + 0) * 256 + tid];
        float wb = gWT[(kk + 1) * 256 + tid];
        float wc = gWT[(kk + 2) * 256 + tid];
        float wd = gWT[(kk + 3) * 256 + tid];
        u64t w01 = pk2(wa, wb);
        u64t w23 = pk2(wc, wd);
#pragma unroll
        for (int r = 0; r < 32; ++r) {
            u64t z01 = *(const u64t*)&zs[r][kk];
            u64t z23 = *(const u64t*)&zs[r][kk + 2];
            acc2[r] = ffma2(z01, w01, acc2[r]);
            acc2[r] = ffma2(z23, w23, acc2[r]);
        }
    }
    float bo = b_out[tid];
#pragma unroll
    for (int r = 0; r < 32; ++r) {
        float lo, hi;
        upk2(acc2[r], lo, hi);
        out[(size_t)(row0 + r) * 256 + tid] = lo + hi + bo;
    }
}

extern "C" void kernel_launch(void* const* d_in, const int* in_sizes, int n_in,
                              void* d_out, int out_size) {
    const float* x         = (const float*)d_in[0];
    const float* log_A     = (const float*)d_in[1];
    const float* Bp        = (const float*)d_in[2];
    const float* Cp        = (const float*)d_in[3];
    const float* log_delta = (const float*)d_in[4];
    const float* skip_D    = (const float*)d_in[5];
    const float* W_out     = (const float*)d_in[6];
    const float* b_out     = (const float*)d_in[7];
    float* out = (float*)d_out;

    const int shm1 = 3 * 64 * 65 * (int)sizeof(float);                    // 49920 B
    const int shm2 = (4 * 64 * 65 + 64 * 33) * (int)sizeof(float);        // 75008 B
    cudaFuncSetAttribute(k1_expm, cudaFuncAttributeMaxDynamicSharedMemorySize, shm1);
    cudaFuncSetAttribute(k2_kernelgen, cudaFuncAttributeMaxDynamicSharedMemorySize, shm2);

    k0_prep<<<1, 256>>>(log_A, log_delta);
    k0b_wt<<<256, 256>>>(W_out);
    k1_expm<<<256, 512, shm1>>>();
    k2_kernelgen<<<256, 512, shm2>>>(Bp, Cp);
    k3_conv<<<512, 256>>>(x);
    k4_out<<<512, 256>>>(x, skip_D, b_out, out);
}